// round 2
// baseline (speedup 1.0000x reference)
#include <cuda_runtime.h>
#include <cuda_bf16.h>
#include <math.h>

#define Bq 4
#define Qn 1024
#define Tn 1024
#define Hn 16
#define Mn 1024
#define Kd 64
#define Vd 64

// ---------------- scratch (static device globals; no runtime alloc) ----------
__device__ float g_q[Bq*Hn*Qn*Kd];     // query * kscale  [b][h][q][d]
__device__ float g_k[Bq*Hn*Tn*Kd];     // key             [b][h][t][d]
__device__ float g_v[Bq*Hn*Tn*Vd];     // value           [b][h][t][d]
__device__ float g_pre[Bq*Hn*Qn*Vd];   // att @ V         [b][h][q][d]
__device__ float g_m[Bq*Hn*Qn];        // running softmax max per row
__device__ float g_l[Bq*Hn*Qn];        // softmax denom per row
__device__ float g_rowocc[Bq*Qn];      // sum_t occu
__device__ float g_colact[Bq*Tn];      // max_q occu
__device__ float g_colsum[Bq*Tn];      // target_marg accumulator

// ---------------- helpers ----------------------------------------------------
__device__ __forceinline__ float warpMax(float v) {
    #pragma unroll
    for (int o = 16; o > 0; o >>= 1) v = fmaxf(v, __shfl_xor_sync(0xffffffffu, v, o));
    return v;
}
__device__ __forceinline__ float warpSum(float v) {
    #pragma unroll
    for (int o = 16; o > 0; o >>= 1) v += __shfl_xor_sync(0xffffffffu, v, o);
    return v;
}

// ---------------- kernel: zero colsum ----------------------------------------
__global__ void init_kernel() {
    int i = blockIdx.x * blockDim.x + threadIdx.x;
    if (i < Bq * Tn) g_colsum[i] = 0.0f;
}

// ---------------- kernel: row occupancy (warp per (b,q) row) -----------------
__global__ __launch_bounds__(256) void rowocc_kernel(const float* __restrict__ tmask,
                                                     const float* __restrict__ qtmask) {
    int warp = threadIdx.x >> 5, lane = threadIdx.x & 31;
    int row = blockIdx.x * 8 + warp;          // row = b*Qn + q
    if (row >= Bq * Qn) return;
    int b = row / Qn;
    float acc = 0.0f;
    const float* qt = qtmask + (size_t)row * Tn;
    const float* tm = tmask + (size_t)b * Tn;
    for (int t = lane; t < Tn; t += 32)
        acc += 1.0f - fmaxf(tm[t], qt[t]);
    acc = warpSum(acc);
    if (lane == 0) g_rowocc[row] = acc;
}

// ---------------- kernel: column activity (thread per (b,t)) -----------------
__global__ __launch_bounds__(256) void colact_kernel(const float* __restrict__ tmask,
                                                     const float* __restrict__ qtmask) {
    int b = blockIdx.y;
    int t = blockIdx.x * blockDim.x + threadIdx.x;
    if (t >= Tn) return;
    float tmv = tmask[b * Tn + t];
    float mx = -1e30f;
    for (int q = 0; q < Qn; q++) {
        float occ = 1.0f - fmaxf(tmv, qtmask[((size_t)(b * Qn + q)) * Tn + t]);
        mx = fmaxf(mx, occ);
    }
    g_colact[b * Tn + t] = mx;
}

// ---------------- kernel: QKV projection GEMM --------------------------------
// grid (64 rowTiles, H, 3). C_h(4096x64) = A(4096x1024) * W_h(1024x64)
__global__ __launch_bounds__(256) void proj_kernel(const float* __restrict__ qin,
                                                   const float* __restrict__ kvin,
                                                   const float* __restrict__ wq,
                                                   const float* __restrict__ wk,
                                                   const float* __restrict__ wv) {
    __shared__ float As[16][64];
    __shared__ float Bs[16][64];
    int which = blockIdx.z;
    int h = blockIdx.y;
    int rowBase = blockIdx.x * 64;
    const float* A = (which == 0) ? qin : kvin;
    const float* W = ((which == 0) ? wq : (which == 1) ? wk : wv) + (size_t)h * Mn * Kd;
    float* C = (which == 0) ? g_q : (which == 1) ? g_k : g_v;

    int tid = threadIdx.x;
    int tx = tid & 15, ty = tid >> 4;
    float acc[4][4];
    #pragma unroll
    for (int i = 0; i < 4; i++)
        #pragma unroll
        for (int j = 0; j < 4; j++) acc[i][j] = 0.0f;

    for (int k0 = 0; k0 < Mn; k0 += 16) {
        {   // A tile: 64 rows x 16 k, stored transposed As[k][row]
            int e = tid * 4;
            int r = e >> 4, c = e & 15;
            float4 v = *(const float4*)&A[(size_t)(rowBase + r) * Mn + k0 + c];
            As[c + 0][r] = v.x; As[c + 1][r] = v.y; As[c + 2][r] = v.z; As[c + 3][r] = v.w;
        }
        {   // W tile: 16 k x 64 d
            int e = tid * 4;
            int r = e >> 6, c = e & 63;
            float4 v = *(const float4*)&W[(size_t)(k0 + r) * Kd + c];
            *(float4*)&Bs[r][c] = v;
        }
        __syncthreads();
        #pragma unroll
        for (int kk = 0; kk < 16; kk++) {
            float4 a = *(float4*)&As[kk][ty * 4];
            float4 bvec = *(float4*)&Bs[kk][tx * 4];
            float av[4] = {a.x, a.y, a.z, a.w};
            float bv[4] = {bvec.x, bvec.y, bvec.z, bvec.w};
            #pragma unroll
            for (int i = 0; i < 4; i++)
                #pragma unroll
                for (int j = 0; j < 4; j++) acc[i][j] += av[i] * bv[j];
        }
        __syncthreads();
    }
    float scale = (which == 0) ? 0.125f : 1.0f;   // kscale = 1/sqrt(64)
    #pragma unroll
    for (int i = 0; i < 4; i++) {
        int r = rowBase + ty * 4 + i;
        int b = r / Qn, rr = r % Qn;
        size_t base = ((size_t)(b * Hn + h) * Qn + rr) * Kd;
        #pragma unroll
        for (int j = 0; j < 4; j++)
            C[base + tx * 4 + j] = acc[i][j] * scale;
    }
}

// ---------------- kernel: flash attention pass 1 -----------------------------
// grid (Q/32, H, B); 256 thr; warp handles 4 query rows.
__global__ __launch_bounds__(256) void attn_kernel(const float* __restrict__ tmask,
                                                   const float* __restrict__ qtmask) {
    __shared__ float ksh[64][65];
    __shared__ float vsh[64][64];
    __shared__ float qsh[32][64];
    int b = blockIdx.z, h = blockIdx.y;
    int qbase = blockIdx.x * 32;
    int tid = threadIdx.x, lane = tid & 31, warp = tid >> 5;

    const float* qptr = g_q + ((size_t)(b * Hn + h) * Qn + qbase) * Kd;
    for (int e = tid * 4; e < 32 * 64; e += 256 * 4)
        *(float4*)&((float*)qsh)[e] = *(const float4*)&qptr[e];

    float m[4], l[4], o0[4], o1[4];
    #pragma unroll
    for (int i = 0; i < 4; i++) { m[i] = -1e30f; l[i] = 0.0f; o0[i] = 0.0f; o1[i] = 0.0f; }

    const float* kbase = g_k + (size_t)(b * Hn + h) * Tn * Kd;
    const float* vbase = g_v + (size_t)(b * Hn + h) * Tn * Vd;
    int ntiles = (qbase + 31) / 64 + 1;   // causal structure of the fixed qtmask

    for (int tile = 0; tile < ntiles; tile++) {
        int t0 = tile * 64;
        __syncthreads();
        for (int e = tid * 4; e < 64 * 64; e += 1024) {
            int tt = e >> 6, d = e & 63;
            float4 kv = *(const float4*)&kbase[(size_t)t0 * 64 + e];
            ksh[tt][d + 0] = kv.x; ksh[tt][d + 1] = kv.y; ksh[tt][d + 2] = kv.z; ksh[tt][d + 3] = kv.w;
            *(float4*)&((float*)vsh)[e] = *(const float4*)&vbase[(size_t)t0 * 64 + e];
        }
        __syncthreads();

        float s0[4] = {0, 0, 0, 0}, s1[4] = {0, 0, 0, 0};
        #pragma unroll 16
        for (int d = 0; d < 64; d++) {
            float k0v = ksh[lane][d], k1v = ksh[lane + 32][d];
            #pragma unroll
            for (int i = 0; i < 4; i++) {
                float qv = qsh[warp * 4 + i][d];
                s0[i] += qv * k0v;
                s1[i] += qv * k1v;
            }
        }
        float p0[4], p1[4];
        #pragma unroll
        for (int i = 0; i < 4; i++) {
            int qrow = qbase + warp * 4 + i;
            int tg0 = t0 + lane, tg1 = t0 + lane + 32;
            const float* qtrow = qtmask + (size_t)(b * Qn + qrow) * Tn;
            float occ0 = 1.0f - fmaxf(tmask[b * Tn + tg0], qtrow[tg0]);
            float occ1 = 1.0f - fmaxf(tmask[b * Tn + tg1], qtrow[tg1]);
            bool a0 = occ0 > 0.0f, a1 = occ1 > 0.0f;
            float ss0 = a0 ? s0[i] : -1e30f;
            float ss1 = a1 ? s1[i] : -1e30f;
            float tmax = warpMax(fmaxf(ss0, ss1));
            float mnew = fmaxf(m[i], tmax);
            float sc = __expf(m[i] - mnew);
            p0[i] = a0 ? __expf(ss0 - mnew) : 0.0f;
            p1[i] = a1 ? __expf(ss1 - mnew) : 0.0f;
            float ps = warpSum(p0[i] + p1[i]);
            l[i] = l[i] * sc + ps;
            m[i] = mnew;
            o0[i] *= sc; o1[i] *= sc;
        }
        #pragma unroll 8
        for (int t = 0; t < 32; t++) {
            float v0 = vsh[t][lane], v1 = vsh[t][lane + 32];
            #pragma unroll
            for (int i = 0; i < 4; i++) {
                float pb = __shfl_sync(0xffffffffu, p0[i], t);
                o0[i] += pb * v0;
                o1[i] += pb * v1;
            }
        }
        #pragma unroll 8
        for (int t = 0; t < 32; t++) {
            float v0 = vsh[t + 32][lane], v1 = vsh[t + 32][lane + 32];
            #pragma unroll
            for (int i = 0; i < 4; i++) {
                float pb = __shfl_sync(0xffffffffu, p1[i], t);
                o0[i] += pb * v0;
                o1[i] += pb * v1;
            }
        }
    }
    #pragma unroll
    for (int i = 0; i < 4; i++) {
        int qrow = qbase + warp * 4 + i;
        float inv = 1.0f / l[i];
        size_t idx = ((size_t)(b * Hn + h) * Qn + qrow) * Vd;
        g_pre[idx + lane]      = o0[i] * inv;
        g_pre[idx + lane + 32] = o1[i] * inv;
        if (lane == 0) {
            g_m[(b * Hn + h) * Qn + qrow] = m[i];
            g_l[(b * Hn + h) * Qn + qrow] = l[i];
        }
    }
}

// ---------------- kernel: column sums (target_marg) pass 2 -------------------
// grid (T/32, H, B); warp handles 4 t-columns; loops q tiles.
__global__ __launch_bounds__(256) void colsum_kernel(const float* __restrict__ tmask,
                                                     const float* __restrict__ qtmask) {
    __shared__ float ksh[32][64];
    __shared__ float qsh[64][65];
    __shared__ float msh[64], lsh[64], rsh[64];
    int b = blockIdx.z, h = blockIdx.y;
    int tb = blockIdx.x * 32;
    int tid = threadIdx.x, lane = tid & 31, warp = tid >> 5;

    const float* kbase = g_k + ((size_t)(b * Hn + h) * Tn + tb) * Kd;
    for (int e = tid * 4; e < 32 * 64; e += 1024)
        *(float4*)&((float*)ksh)[e] = *(const float4*)&kbase[e];

    float csum[4] = {0, 0, 0, 0};
    int hq = (b * Hn + h) * Qn;
    const float* qmat = g_q + (size_t)hq * Kd;

    for (int q0 = (tb / 64) * 64; q0 < Qn; q0 += 64) {
        __syncthreads();
        for (int e = tid * 4; e < 64 * 64; e += 1024) {
            int qq = e >> 6, d = e & 63;
            float4 v = *(const float4*)&qmat[(size_t)q0 * 64 + e];
            qsh[qq][d + 0] = v.x; qsh[qq][d + 1] = v.y; qsh[qq][d + 2] = v.z; qsh[qq][d + 3] = v.w;
        }
        if (tid < 64) {
            msh[tid] = g_m[hq + q0 + tid];
            lsh[tid] = g_l[hq + q0 + tid];
            rsh[tid] = g_rowocc[b * Qn + q0 + tid];
        }
        __syncthreads();

        float s0[4] = {0, 0, 0, 0}, s1[4] = {0, 0, 0, 0};
        #pragma unroll 16
        for (int d = 0; d < 64; d++) {
            float qv0 = qsh[lane][d], qv1 = qsh[lane + 32][d];
            #pragma unroll
            for (int i = 0; i < 4; i++) {
                float kv = ksh[warp * 4 + i][d];
                s0[i] += kv * qv0;
                s1[i] += kv * qv1;
            }
        }
        #pragma unroll
        for (int i = 0; i < 4; i++) {
            int t = tb + warp * 4 + i;
            float tmv = tmask[b * Tn + t];
            int qg0 = q0 + lane, qg1 = q0 + lane + 32;
            float occ0 = 1.0f - fmaxf(tmv, qtmask[(size_t)(b * Qn + qg0) * Tn + t]);
            float occ1 = 1.0f - fmaxf(tmv, qtmask[(size_t)(b * Qn + qg1) * Tn + t]);
            if (occ0 > 0.0f) csum[i] += __expf(s0[i] - msh[lane]) / lsh[lane] * rsh[lane];
            if (occ1 > 0.0f) csum[i] += __expf(s1[i] - msh[lane + 32]) / lsh[lane + 32] * rsh[lane + 32];
        }
    }
    #pragma unroll
    for (int i = 0; i < 4; i++) {
        float v = warpSum(csum[i]);
        if (lane == 0) atomicAdd(&g_colsum[b * Tn + tb + warp * 4 + i], v);
    }
}

// ---------------- kernel: entropy --------------------------------------------
__global__ __launch_bounds__(256) void entropy_kernel(float* __restrict__ eout) {
    int b = blockIdx.x, tid = threadIdx.x;
    int lane = tid & 31, warp = tid >> 5;
    __shared__ float sh0[8], sh1[8];
    float sm = 0.0f, sa = 0.0f;
    for (int t = tid; t < Tn; t += 256) {
        sm += g_colsum[b * Tn + t];
        sa += g_colact[b * Tn + t];
    }
    sm = warpSum(sm); sa = warpSum(sa);
    if (lane == 0) { sh0[warp] = sm; sh1[warp] = sa; }
    __syncthreads();
    float tsum = 0.0f, csum = 0.0f;
    #pragma unroll
    for (int w = 0; w < 8; w++) { tsum += sh0[w]; csum += sh1[w]; }
    __syncthreads();
    float ent = 0.0f;
    for (int t = tid; t < Tn; t += 256) {
        float p = g_colsum[b * Tn + t] / tsum;
        if (g_colact[b * Tn + t] > 0.0f && p > 0.0f) ent -= p * log2f(p);
    }
    ent = warpSum(ent);
    if (lane == 0) sh0[warp] = ent;
    __syncthreads();
    if (tid == 0) {
        float e = 0.0f;
        #pragma unroll
        for (int w = 0; w < 8; w++) e += sh0[w];
        eout[b] = e / log2f(csum);
    }
}

// ---------------- kernel: output projection GEMM -----------------------------
// out(4096x1024) = pre(4096 x 1024[h*64+d]) * wo(1024x1024); epilogue *(1-qmask)
__global__ __launch_bounds__(256) void outproj_kernel(const float* __restrict__ qmask,
                                                      const float* __restrict__ wo,
                                                      float* __restrict__ out) {
    __shared__ float As[16][64];
    __shared__ float Bs[16][64];
    int rowBase = blockIdx.x * 64;
    int colBase = blockIdx.y * 64;
    int tid = threadIdx.x;
    int tx = tid & 15, ty = tid >> 4;
    float acc[4][4];
    #pragma unroll
    for (int i = 0; i < 4; i++)
        #pragma unroll
        for (int j = 0; j < 4; j++) acc[i][j] = 0.0f;

    for (int k0 = 0; k0 < Hn * Vd; k0 += 16) {
        {   // A tile (pre, gathered layout)
            int e = tid * 4;
            int r = e >> 4, c = e & 15;
            int rg = rowBase + r;
            int b = rg / Qn, qq = rg % Qn;
            int k = k0 + c;
            int h = k >> 6, d = k & 63;
            float4 v = *(const float4*)&g_pre[((size_t)(b * Hn + h) * Qn + qq) * Vd + d];
            As[c + 0][r] = v.x; As[c + 1][r] = v.y; As[c + 2][r] = v.z; As[c + 3][r] = v.w;
        }
        {   // wo tile
            int e = tid * 4;
            int r = e >> 6, c = e & 63;
            float4 v = *(const float4*)&wo[(size_t)(k0 + r) * Mn + colBase + c];
            *(float4*)&Bs[r][c] = v;
        }
        __syncthreads();
        #pragma unroll
        for (int kk = 0; kk < 16; kk++) {
            float4 a = *(float4*)&As[kk][ty * 4];
            float4 bvec = *(float4*)&Bs[kk][tx * 4];
            float av[4] = {a.x, a.y, a.z, a.w};
            float bv[4] = {bvec.x, bvec.y, bvec.z, bvec.w};
            #pragma unroll
            for (int i = 0; i < 4; i++)
                #pragma unroll
                for (int j = 0; j < 4; j++) acc[i][j] += av[i] * bv[j];
        }
        __syncthreads();
    }
    #pragma unroll
    for (int i = 0; i < 4; i++) {
        int r = rowBase + ty * 4 + i;
        int b = r / Qn, qq = r % Qn;
        float w = 1.0f - qmask[b * Qn + qq];
        #pragma unroll
        for (int j = 0; j < 4; j++)
            out[(size_t)r * Mn + colBase + tx * 4 + j] = acc[i][j] * w;
    }
}

// ---------------- launch ------------------------------------------------------
extern "C" void kernel_launch(void* const* d_in, const int* in_sizes, int n_in,
                              void* d_out, int out_size) {
    const float* qinput  = (const float*)d_in[0];
    const float* kvinput = (const float*)d_in[1];
    const float* qmask   = (const float*)d_in[2];
    const float* tmask   = (const float*)d_in[3];
    const float* qtmask  = (const float*)d_in[4];
    const float* wq      = (const float*)d_in[5];
    const float* wk      = (const float*)d_in[6];
    const float* wv      = (const float*)d_in[7];
    const float* wo      = (const float*)d_in[8];
    float* out  = (float*)d_out;
    float* eout = out + (out_size - Bq);

    init_kernel<<<(Bq * Tn + 255) / 256, 256>>>();
    rowocc_kernel<<<(Bq * Qn) / 8, 256>>>(tmask, qtmask);
    colact_kernel<<<dim3(Tn / 256, Bq), 256>>>(tmask, qtmask);
    proj_kernel<<<dim3((Bq * Qn) / 64, Hn, 3), 256>>>(qinput, kvinput, wq, wk, wv);
    attn_kernel<<<dim3(Qn / 32, Hn, Bq), 256>>>(tmask, qtmask);
    colsum_kernel<<<dim3(Tn / 32, Hn, Bq), 256>>>(tmask, qtmask);
    entropy_kernel<<<Bq, 256>>>(eout);
    outproj_kernel<<<dim3((Bq * Qn) / 64, Mn / 64), 256>>>(qmask, wo, out);
}

// round 6
// speedup vs baseline: 1.1145x; 1.1145x over previous
#include <cuda_runtime.h>
#include <math.h>

#define Bq 4
#define Qn 1024
#define Tn 1024
#define Hn 16
#define Mn 1024
#define Kd 64
#define Vd 64

typedef unsigned long long u64;

// ---------------- scratch (static device globals; no runtime alloc) ----------
__device__ float g_q[Bq*Hn*Qn*Kd];     // query * kscale  [b][h][q][d]
__device__ float g_k[Bq*Hn*Tn*Kd];     // key             [b][h][t][d]
__device__ float g_v[Bq*Hn*Tn*Vd];     // value           [b][h][t][d]
__device__ float g_pre[Bq*Hn*Qn*Vd];   // att @ V         [b][h][q][d]
__device__ float g_m[Bq*Hn*Qn];        // softmax max per row
__device__ float g_l[Bq*Hn*Qn];        // softmax denom per row
__device__ float g_rowocc[Bq*Qn];      // sum_t occu
__device__ float g_colact[Bq*Tn];      // max_q occu
__device__ float g_colsum[Bq*Tn];      // target_marg accumulator

// ---------------- f32x2 helpers ----------------------------------------------
__device__ __forceinline__ u64 dup2(float v) {
    u64 d;
    asm("mov.b64 %0, {%1, %1};" : "=l"(d) : "r"(__float_as_uint(v)));
    return d;
}
__device__ __forceinline__ void fma2(u64 &acc, u64 a, u64 b) {
    asm("fma.rn.f32x2 %0, %1, %2, %3;" : "=l"(acc) : "l"(a), "l"(b), "l"(acc));
}
__device__ __forceinline__ u64 mul2(u64 a, u64 b) {
    u64 d;
    asm("mul.rn.f32x2 %0, %1, %2;" : "=l"(d) : "l"(a), "l"(b));
    return d;
}
__device__ __forceinline__ float2 unpack2(u64 v) {
    unsigned lo, hi;
    asm("mov.b64 {%0, %1}, %2;" : "=r"(lo), "=r"(hi) : "l"(v));
    return make_float2(__uint_as_float(lo), __uint_as_float(hi));
}

__device__ __forceinline__ float warpSum(float v) {
    #pragma unroll
    for (int o = 16; o > 0; o >>= 1) v += __shfl_xor_sync(0xffffffffu, v, o);
    return v;
}

// ---------------- small kernels -----------------------------------------------
__global__ void init_kernel() {
    int i = blockIdx.x * blockDim.x + threadIdx.x;
    if (i < Bq * Tn) g_colsum[i] = 0.0f;
}

__global__ __launch_bounds__(256) void rowocc_kernel(const float* __restrict__ tmask,
                                                     const float* __restrict__ qtmask) {
    int warp = threadIdx.x >> 5, lane = threadIdx.x & 31;
    int row = blockIdx.x * 8 + warp;
    if (row >= Bq * Qn) return;
    int b = row / Qn;
    float acc = 0.0f;
    const float* qt = qtmask + (size_t)row * Tn;
    const float* tm = tmask + (size_t)b * Tn;
    for (int t = lane; t < Tn; t += 32)
        acc += 1.0f - fmaxf(tm[t], qt[t]);
    acc = warpSum(acc);
    if (lane == 0) g_rowocc[row] = acc;
}

__global__ __launch_bounds__(256) void colact_kernel(const float* __restrict__ tmask,
                                                     const float* __restrict__ qtmask) {
    int b = blockIdx.y;
    int t = blockIdx.x * blockDim.x + threadIdx.x;
    if (t >= Tn) return;
    float tmv = tmask[b * Tn + t];
    float mx = -1e30f;
    for (int q = 0; q < Qn; q++) {
        float occ = 1.0f - fmaxf(tmv, qtmask[((size_t)(b * Qn + q)) * Tn + t]);
        mx = fmaxf(mx, occ);
    }
    g_colact[b * Tn + t] = mx;
}

// ---------------- fused QKV projection: 128x128 tiles, f32x2 ------------------
// grid (32, 24): y<8 -> Q-GEMM cols y*128 of 1024; y in [8,16) -> K; [16,24) -> V
__global__ __launch_bounds__(256) void proj2_kernel(const float* __restrict__ qin,
                                                    const float* __restrict__ kvin,
                                                    const float* __restrict__ wq,
                                                    const float* __restrict__ wk,
                                                    const float* __restrict__ wv) {
    __shared__ float As[16][128];   // k-major, transposed
    __shared__ float Bs[16][128];
    int y = blockIdx.y;
    int grp = (y < 8) ? 0 : ((y < 16) ? 1 : 2);
    int cn = (y - grp * 8) * 128;
    const float* A = grp ? kvin : qin;
    const float* W = (grp == 0) ? wq : (grp == 1) ? wk : wv;
    float* C = (grp == 0) ? g_q : (grp == 1) ? g_k : g_v;
    float scale = (grp == 0) ? 0.125f : 1.0f;
    int rowBase = blockIdx.x * 128;
    int tid = threadIdx.x;
    int tx = tid & 15, ty = tid >> 4;

    u64 acc[8][4];
    #pragma unroll
    for (int i = 0; i < 8; i++)
        #pragma unroll
        for (int j = 0; j < 4; j++) acc[i][j] = 0ull;

    int arow = tid >> 1, akh = (tid & 1) * 8;

    for (int k0 = 0; k0 < Mn; k0 += 16) {
        {   // A tile: 128 rows x 16 k, transposed store
            const float* ap = &A[(size_t)(rowBase + arow) * Mn + k0 + akh];
            float4 a0 = *(const float4*)&ap[0];
            float4 a1 = *(const float4*)&ap[4];
            As[akh + 0][arow] = a0.x; As[akh + 1][arow] = a0.y;
            As[akh + 2][arow] = a0.z; As[akh + 3][arow] = a0.w;
            As[akh + 4][arow] = a1.x; As[akh + 5][arow] = a1.y;
            As[akh + 6][arow] = a1.z; As[akh + 7][arow] = a1.w;
        }
        #pragma unroll
        for (int half = 0; half < 2; half++) {   // B tile: 16 k x 128 cols
            int f = tid + half * 256;
            int r = f >> 5, cs = (f & 31) * 4;
            int c = cn + cs;
            int h = c >> 6, d = c & 63;
            float4 bv = *(const float4*)&W[(size_t)h * Mn * Kd + (size_t)(k0 + r) * Kd + d];
            *(float4*)&Bs[r][cs] = bv;
        }
        __syncthreads();
        #pragma unroll
        for (int kk = 0; kk < 16; kk++) {
            float4 a0 = *(const float4*)&As[kk][ty * 8];
            float4 a1 = *(const float4*)&As[kk][ty * 8 + 4];
            ulonglong2 b0 = *(const ulonglong2*)&Bs[kk][tx * 8];
            ulonglong2 b1 = *(const ulonglong2*)&Bs[kk][tx * 8 + 4];
            u64 ad[8];
            ad[0] = dup2(a0.x); ad[1] = dup2(a0.y); ad[2] = dup2(a0.z); ad[3] = dup2(a0.w);
            ad[4] = dup2(a1.x); ad[5] = dup2(a1.y); ad[6] = dup2(a1.z); ad[7] = dup2(a1.w);
            #pragma unroll
            for (int i = 0; i < 8; i++) {
                fma2(acc[i][0], ad[i], b0.x);
                fma2(acc[i][1], ad[i], b0.y);
                fma2(acc[i][2], ad[i], b1.x);
                fma2(acc[i][3], ad[i], b1.y);
            }
        }
        __syncthreads();
    }
    #pragma unroll
    for (int i = 0; i < 8; i++) {
        int r = rowBase + ty * 8 + i;
        int b = r >> 10, qq = r & 1023;
        #pragma unroll
        for (int j = 0; j < 4; j++) {
            int c = cn + tx * 8 + j * 2;
            int h = c >> 6, d = c & 63;
            float2 v = unpack2(acc[i][j]);
            float* dst = &C[(((size_t)(b * Hn + h)) * Qn + qq) * Kd + d];
            dst[0] = v.x * scale;
            dst[1] = v.y * scale;
        }
    }
}

// ---------------- flash attention: 64q-tile, GEMM-style, f32x2 ----------------
// grid (16, H, B), 256 threads; thread (tx,ty): q rows ty*4.., d/t cols tx*4..
__global__ __launch_bounds__(256) void attn2_kernel(const float* __restrict__ tmask,
                                                    const float* __restrict__ qtmask) {
    extern __shared__ float smem[];
    float (*Qs)[68] = (float(*)[68])smem;                     // d-major [64d][64q]
    float (*Ks)[68] = (float(*)[68])(smem + 64 * 68);         // d-major [64d][64t]
    float* Vs = smem + 2 * 64 * 68;                           // t-major [64t][64d]
    float (*Ps)[64] = (float(*)[64])(smem + 2 * 64 * 68 + 64 * 64);  // [64t][64q]

    int b = blockIdx.z, h = blockIdx.y;
    int qb = (gridDim.x - 1 - blockIdx.x) * 64;   // longest blocks first
    int bh = b * Hn + h;
    int tid = threadIdx.x, tx = tid & 15, ty = tid >> 4;

    const float* qsrc = g_q + ((size_t)bh * Qn + qb) * Kd;
    #pragma unroll
    for (int it = 0; it < 4; it++) {
        int f = it * 256 + tid;
        int q = f >> 4, ds = (f & 15) * 4;
        float4 v = *(const float4*)&qsrc[q * Kd + ds];
        Qs[ds + 0][q] = v.x; Qs[ds + 1][q] = v.y; Qs[ds + 2][q] = v.z; Qs[ds + 3][q] = v.w;
    }

    float m[4], l[4];
    u64 od[4][2];
    #pragma unroll
    for (int i = 0; i < 4; i++) { m[i] = -1e30f; l[i] = 0.0f; od[i][0] = 0ull; od[i][1] = 0ull; }

    const float* kbase = g_k + (size_t)bh * Tn * Kd;
    const float* vbase = g_v + (size_t)bh * Tn * Vd;
    int nt = qb / 64 + 1;

    for (int tile = 0; tile < nt; tile++) {
        int t0 = tile * 64;
        __syncthreads();
        #pragma unroll
        for (int it = 0; it < 4; it++) {
            int f = it * 256 + tid;
            int t = f >> 4, ds = (f & 15) * 4;
            float4 kv = *(const float4*)&kbase[(size_t)(t0 + t) * Kd + ds];
            Ks[ds + 0][t] = kv.x; Ks[ds + 1][t] = kv.y; Ks[ds + 2][t] = kv.z; Ks[ds + 3][t] = kv.w;
            *(float4*)&Vs[f * 4] = *(const float4*)&vbase[(size_t)t0 * Vd + f * 4];
        }
        __syncthreads();

        // ---- S = Q K^T (outer product over d) ----
        u64 sd[4][2];
        #pragma unroll
        for (int i = 0; i < 4; i++) { sd[i][0] = 0ull; sd[i][1] = 0ull; }
        #pragma unroll 8
        for (int d = 0; d < 64; d++) {
            float4 a = *(const float4*)&Qs[d][ty * 4];
            ulonglong2 kp = *(const ulonglong2*)&Ks[d][tx * 4];
            u64 a0 = dup2(a.x), a1 = dup2(a.y), a2 = dup2(a.z), a3 = dup2(a.w);
            fma2(sd[0][0], a0, kp.x); fma2(sd[0][1], a0, kp.y);
            fma2(sd[1][0], a1, kp.x); fma2(sd[1][1], a1, kp.y);
            fma2(sd[2][0], a2, kp.x); fma2(sd[2][1], a2, kp.y);
            fma2(sd[3][0], a3, kp.x); fma2(sd[3][1], a3, kp.y);
        }
        float S[4][4];
        #pragma unroll
        for (int i = 0; i < 4; i++) {
            float2 v0 = unpack2(sd[i][0]), v1 = unpack2(sd[i][1]);
            S[i][0] = v0.x; S[i][1] = v0.y; S[i][2] = v1.x; S[i][3] = v1.y;
        }

        // ---- online softmax over row groups of 16 threads ----
        float4 tm4 = *(const float4*)&tmask[b * Tn + t0 + tx * 4];
        float tma[4] = {tm4.x, tm4.y, tm4.z, tm4.w};
        #pragma unroll
        for (int i = 0; i < 4; i++) {
            int qg = qb + ty * 4 + i;
            float4 qt4 = *(const float4*)&qtmask[((size_t)(b * Qn + qg)) * Tn + t0 + tx * 4];
            float qta[4] = {qt4.x, qt4.y, qt4.z, qt4.w};
            float rmax = -1e30f;
            bool act[4];
            #pragma unroll
            for (int j = 0; j < 4; j++) {
                act[j] = (1.0f - fmaxf(tma[j], qta[j])) > 0.0f;
                S[i][j] = act[j] ? S[i][j] : -1e30f;
                rmax = fmaxf(rmax, S[i][j]);
            }
            #pragma unroll
            for (int o = 8; o > 0; o >>= 1)
                rmax = fmaxf(rmax, __shfl_xor_sync(0xffffffffu, rmax, o));
            float mnew = fmaxf(m[i], rmax);
            float sc = __expf(m[i] - mnew);
            float p[4], ps = 0.0f;
            #pragma unroll
            for (int j = 0; j < 4; j++) {
                p[j] = act[j] ? __expf(S[i][j] - mnew) : 0.0f;
                ps += p[j];
            }
            #pragma unroll
            for (int o = 8; o > 0; o >>= 1)
                ps += __shfl_xor_sync(0xffffffffu, ps, o);
            l[i] = l[i] * sc + ps;
            m[i] = mnew;
            u64 scd = dup2(sc);
            od[i][0] = mul2(od[i][0], scd);
            od[i][1] = mul2(od[i][1], scd);
            Ps[tx * 4 + 0][ty * 4 + i] = p[0];
            Ps[tx * 4 + 1][ty * 4 + i] = p[1];
            Ps[tx * 4 + 2][ty * 4 + i] = p[2];
            Ps[tx * 4 + 3][ty * 4 + i] = p[3];
        }
        __syncthreads();

        // ---- O += P V (outer product over t) ----
        #pragma unroll 8
        for (int t = 0; t < 64; t++) {
            float4 pp = *(const float4*)&Ps[t][ty * 4];
            ulonglong2 vp = *(const ulonglong2*)&Vs[t * 64 + tx * 4];
            u64 p0 = dup2(pp.x), p1 = dup2(pp.y), p2 = dup2(pp.z), p3 = dup2(pp.w);
            fma2(od[0][0], p0, vp.x); fma2(od[0][1], p0, vp.y);
            fma2(od[1][0], p1, vp.x); fma2(od[1][1], p1, vp.y);
            fma2(od[2][0], p2, vp.x); fma2(od[2][1], p2, vp.y);
            fma2(od[3][0], p3, vp.x); fma2(od[3][1], p3, vp.y);
        }
    }

    #pragma unroll
    for (int i = 0; i < 4; i++) {
        int qg = qb + ty * 4 + i;
        float inv = 1.0f / l[i];
        float2 v0 = unpack2(od[i][0]), v1 = unpack2(od[i][1]);
        float4 o = make_float4(v0.x * inv, v0.y * inv, v1.x * inv, v1.y * inv);
        *(float4*)&g_pre[((size_t)bh * Qn + qg) * Vd + tx * 4] = o;
        if (tx == 0) {
            g_m[bh * Qn + qg] = m[i];
            g_l[bh * Qn + qg] = l[i];
        }
    }
}

// ---------------- column sums (target_marg) pass 2 ----------------------------
__global__ __launch_bounds__(256) void colsum_kernel(const float* __restrict__ tmask,
                                                     const float* __restrict__ qtmask) {
    __shared__ float ksh[32][64];
    __shared__ float qsh[64][65];
    __shared__ float msh[64], lsh[64], rsh[64];
    int b = blockIdx.z, h = blockIdx.y;
    int tb = blockIdx.x * 32;
    int tid = threadIdx.x, lane = tid & 31, warp = tid >> 5;

    const float* kbase = g_k + ((size_t)(b * Hn + h) * Tn + tb) * Kd;
    for (int e = tid * 4; e < 32 * 64; e += 1024)
        *(float4*)&((float*)ksh)[e] = *(const float4*)&kbase[e];

    float csum[4] = {0, 0, 0, 0};
    int hq = (b * Hn + h) * Qn;
    const float* qmat = g_q + (size_t)hq * Kd;

    for (int q0 = (tb / 64) * 64; q0 < Qn; q0 += 64) {
        __syncthreads();
        for (int e = tid * 4; e < 64 * 64; e += 1024) {
            int qq = e >> 6, d = e & 63;
            float4 v = *(const float4*)&qmat[(size_t)q0 * 64 + e];
            qsh[qq][d + 0] = v.x; qsh[qq][d + 1] = v.y; qsh[qq][d + 2] = v.z; qsh[qq][d + 3] = v.w;
        }
        if (tid < 64) {
            msh[tid] = g_m[hq + q0 + tid];
            lsh[tid] = g_l[hq + q0 + tid];
            rsh[tid] = g_rowocc[b * Qn + q0 + tid];
        }
        __syncthreads();

        float s0[4] = {0, 0, 0, 0}, s1[4] = {0, 0, 0, 0};
        #pragma unroll 16
        for (int d = 0; d < 64; d++) {
            float qv0 = qsh[lane][d], qv1 = qsh[lane + 32][d];
            #pragma unroll
            for (int i = 0; i < 4; i++) {
                float kv = ksh[warp * 4 + i][d];
                s0[i] += kv * qv0;
                s1[i] += kv * qv1;
            }
        }
        #pragma unroll
        for (int i = 0; i < 4; i++) {
            int t = tb + warp * 4 + i;
            float tmv = tmask[b * Tn + t];
            int qg0 = q0 + lane, qg1 = q0 + lane + 32;
            float occ0 = 1.0f - fmaxf(tmv, qtmask[(size_t)(b * Qn + qg0) * Tn + t]);
            float occ1 = 1.0f - fmaxf(tmv, qtmask[(size_t)(b * Qn + qg1) * Tn + t]);
            if (occ0 > 0.0f) csum[i] += __expf(s0[i] - msh[lane]) / lsh[lane] * rsh[lane];
            if (occ1 > 0.0f) csum[i] += __expf(s1[i] - msh[lane + 32]) / lsh[lane + 32] * rsh[lane + 32];
        }
    }
    #pragma unroll
    for (int i = 0; i < 4; i++) {
        float v = warpSum(csum[i]);
        if (lane == 0) atomicAdd(&g_colsum[b * Tn + tb + warp * 4 + i], v);
    }
}

// ---------------- entropy -----------------------------------------------------
__global__ __launch_bounds__(256) void entropy_kernel(float* __restrict__ eout) {
    int b = blockIdx.x, tid = threadIdx.x;
    int lane = tid & 31, warp = tid >> 5;
    __shared__ float sh0[8], sh1[8];
    float sm = 0.0f, sa = 0.0f;
    for (int t = tid; t < Tn; t += 256) {
        sm += g_colsum[b * Tn + t];
        sa += g_colact[b * Tn + t];
    }
    sm = warpSum(sm); sa = warpSum(sa);
    if (lane == 0) { sh0[warp] = sm; sh1[warp] = sa; }
    __syncthreads();
    float tsum = 0.0f, csum = 0.0f;
    #pragma unroll
    for (int w = 0; w < 8; w++) { tsum += sh0[w]; csum += sh1[w]; }
    __syncthreads();
    float ent = 0.0f;
    for (int t = tid; t < Tn; t += 256) {
        float p = g_colsum[b * Tn + t] / tsum;
        if (g_colact[b * Tn + t] > 0.0f && p > 0.0f) ent -= p * log2f(p);
    }
    ent = warpSum(ent);
    if (lane == 0) sh0[warp] = ent;
    __syncthreads();
    if (tid == 0) {
        float e = 0.0f;
        #pragma unroll
        for (int w = 0; w < 8; w++) e += sh0[w];
        eout[b] = e / log2f(csum);
    }
}

// ---------------- output projection: 128x128 tiles, f32x2 ---------------------
__global__ __launch_bounds__(256) void outproj2_kernel(const float* __restrict__ qmask,
                                                       const float* __restrict__ wo,
                                                       float* __restrict__ out) {
    __shared__ float As[16][128];
    __shared__ float Bs[16][128];
    int rowBase = blockIdx.x * 128;
    int cn = blockIdx.y * 128;
    int tid = threadIdx.x;
    int tx = tid & 15, ty = tid >> 4;

    u64 acc[8][4];
    #pragma unroll
    for (int i = 0; i < 8; i++)
        #pragma unroll
        for (int j = 0; j < 4; j++) acc[i][j] = 0ull;

    int arow = tid >> 1, akh = (tid & 1) * 8;
    int ab = (rowBase + arow) >> 10, aq = (rowBase + arow) & 1023;

    for (int k0 = 0; k0 < Hn * Vd; k0 += 16) {
        {   // A tile from g_pre (gathered head layout), transposed store
            int k = k0 + akh;
            int h = k >> 6, d = k & 63;
            const float* ap = &g_pre[((size_t)(ab * Hn + h) * Qn + aq) * Vd + d];
            float4 a0 = *(const float4*)&ap[0];
            float4 a1 = *(const float4*)&ap[4];
            As[akh + 0][arow] = a0.x; As[akh + 1][arow] = a0.y;
            As[akh + 2][arow] = a0.z; As[akh + 3][arow] = a0.w;
            As[akh + 4][arow] = a1.x; As[akh + 5][arow] = a1.y;
            As[akh + 6][arow] = a1.z; As[akh + 7][arow] = a1.w;
        }
        #pragma unroll
        for (int half = 0; half < 2; half++) {
            int f = tid + half * 256;
            int r = f >> 5, cs = (f & 31) * 4;
            float4 bv = *(const float4*)&wo[(size_t)(k0 + r) * Mn + cn + cs];
            *(float4*)&Bs[r][cs] = bv;
        }
        __syncthreads();
        #pragma unroll
        for (int kk = 0; kk < 16; kk++) {
            float4 a0 = *(const float4*)&As[kk][ty * 8];
            float4 a1 = *(const float4*)&As[kk][ty * 8 + 4];
            ulonglong2 b0 = *(const ulonglong2*)&Bs[kk][tx * 8];
            ulonglong2 b1 = *(const ulonglong2*)&Bs[kk][tx * 8 + 4];
            u64 ad[8];
            ad[0] = dup2(a0.x); ad[1] = dup2(a0.y); ad[2] = dup2(a0.z); ad[3] = dup2(a0.w);
            ad[4] = dup2(a1.x); ad[5] = dup2(a1.y); ad[6] = dup2(a1.z); ad[7] = dup2(a1.w);
            #pragma unroll
            for (int i = 0; i < 8; i++) {
                fma2(acc[i][0], ad[i], b0.x);
                fma2(acc[i][1], ad[i], b0.y);
                fma2(acc[i][2], ad[i], b1.x);
                fma2(acc[i][3], ad[i], b1.y);
            }
        }
        __syncthreads();
    }
    #pragma unroll
    for (int i = 0; i < 8; i++) {
        int r = rowBase + ty * 8 + i;
        int b = r >> 10, qq = r & 1023;
        float w = 1.0f - qmask[b * Qn + qq];
        #pragma unroll
        for (int j = 0; j < 4; j++) {
            int c = cn + tx * 8 + j * 2;
            float2 v = unpack2(acc[i][j]);
            out[(size_t)r * Mn + c]     = v.x * w;
            out[(size_t)r * Mn + c + 1] = v.y * w;
        }
    }
}

// ---------------- launch ------------------------------------------------------
extern "C" void kernel_launch(void* const* d_in, const int* in_sizes, int n_in,
                              void* d_out, int out_size) {
    const float* qinput  = (const float*)d_in[0];
    const float* kvinput = (const float*)d_in[1];
    const float* qmask   = (const float*)d_in[2];
    const float* tmask   = (const float*)d_in[3];
    const float* qtmask  = (const float*)d_in[4];
    const float* wq      = (const float*)d_in[5];
    const float* wk      = (const float*)d_in[6];
    const float* wv      = (const float*)d_in[7];
    const float* wo      = (const float*)d_in[8];
    float* out  = (float*)d_out;
    float* eout = out + (out_size - Bq);

    const int ATTN_SMEM = (2 * 64 * 68 + 2 * 64 * 64) * 4;   // 67584 B
    // Unconditional every call: idempotent, deterministic, non-allocating.
    cudaFuncSetAttribute(attn2_kernel, cudaFuncAttributeMaxDynamicSharedMemorySize, ATTN_SMEM);

    init_kernel<<<(Bq * Tn + 255) / 256, 256>>>();
    rowocc_kernel<<<(Bq * Qn) / 8, 256>>>(tmask, qtmask);
    colact_kernel<<<dim3(Tn / 256, Bq), 256>>>(tmask, qtmask);
    proj2_kernel<<<dim3(32, 24), 256>>>(qinput, kvinput, wq, wk, wv);
    attn2_kernel<<<dim3(Qn / 64, Hn, Bq), 256, ATTN_SMEM>>>(tmask, qtmask);
    colsum_kernel<<<dim3(Tn / 32, Hn, Bq), 256>>>(tmask, qtmask);
    entropy_kernel<<<Bq, 256>>>(eout);
    outproj2_kernel<<<dim3(32, 8), 256>>>(qmask, wo, out);
}